// round 16
// baseline (speedup 1.0000x reference)
#include <cuda_runtime.h>
#include <cuda_fp16.h>
#include <cstdint>

#define BATCH   4
#define SEQ     4096
#define DIN     1024
#define DINNER  128
#define DOUT    1024
#define QKVN    384
#define M_TOTAL (BATCH * SEQ)
// SCALE * log2(e): softmax runs in base-2 domain
#define QSCL    0.12751744f

// Scratch
__device__ __half g_x16[(size_t)M_TOTAL * DIN];
__device__ __half g_wqh[QKVN * DIN];
__device__ __half g_woh[DOUT * DINNER];
__device__ __half g_q[(size_t)M_TOTAL * DINNER];
__device__ __half g_k[(size_t)M_TOTAL * DINNER];
__device__ __half g_v[(size_t)M_TOTAL * DINNER];
__device__ __half g_ao[(size_t)M_TOTAL * DINNER];
__device__ float g_po[(size_t)BATCH * 64 * 4 * 64 * DINNER];
__device__ float g_pm[BATCH * 64 * 4 * 64];
__device__ float g_pl[BATCH * 64 * 4 * 64];

// ---------------------------------------------------------------------------
// PTX helpers
// ---------------------------------------------------------------------------
__device__ __forceinline__ uint32_t smem_u32(const void* p) {
    uint32_t a;
    asm("{ .reg .u64 t; cvta.to.shared.u64 t, %1; cvt.u32.u64 %0, t; }"
        : "=r"(a) : "l"(p));
    return a;
}
__device__ __forceinline__ void cpa16(uint32_t dst, const void* src) {
    asm volatile("cp.async.cg.shared.global [%0], [%1], 16;"
                 :: "r"(dst), "l"(src));
}
__device__ __forceinline__ void cp_commit() {
    asm volatile("cp.async.commit_group;" ::: "memory");
}
__device__ __forceinline__ void cp_wait1() {
    asm volatile("cp.async.wait_group 1;" ::: "memory");
}
__device__ __forceinline__ void cp_wait0() {
    asm volatile("cp.async.wait_group 0;" ::: "memory");
}
__device__ __forceinline__ void ldsm4(uint32_t* r, uint32_t a) {
    asm volatile("ldmatrix.sync.aligned.m8n8.x4.shared.b16 {%0,%1,%2,%3}, [%4];"
        : "=r"(r[0]), "=r"(r[1]), "=r"(r[2]), "=r"(r[3]) : "r"(a));
}
__device__ __forceinline__ void ldsm4t(uint32_t* r, uint32_t a) {
    asm volatile("ldmatrix.sync.aligned.m8n8.x4.trans.shared.b16 {%0,%1,%2,%3}, [%4];"
        : "=r"(r[0]), "=r"(r[1]), "=r"(r[2]), "=r"(r[3]) : "r"(a));
}
__device__ __forceinline__ void ldsm2(uint32_t* r, uint32_t a) {
    asm volatile("ldmatrix.sync.aligned.m8n8.x2.shared.b16 {%0,%1}, [%2];"
        : "=r"(r[0]), "=r"(r[1]) : "r"(a));
}
__device__ __forceinline__ void mma_f16(float* c, const uint32_t* a,
                                        const uint32_t* b) {
    asm volatile(
        "mma.sync.aligned.m16n8k16.row.col.f32.f16.f16.f32 "
        "{%0,%1,%2,%3}, {%4,%5,%6,%7}, {%8,%9}, {%0,%1,%2,%3};"
        : "+f"(c[0]), "+f"(c[1]), "+f"(c[2]), "+f"(c[3])
        : "r"(a[0]), "r"(a[1]), "r"(a[2]), "r"(a[3]), "r"(b[0]), "r"(b[1]));
}
__device__ __forceinline__ void mma_f16b(float* c, const uint32_t* a,
                                         uint32_t b0, uint32_t b1) {
    asm volatile(
        "mma.sync.aligned.m16n8k16.row.col.f32.f16.f16.f32 "
        "{%0,%1,%2,%3}, {%4,%5,%6,%7}, {%8,%9}, {%0,%1,%2,%3};"
        : "+f"(c[0]), "+f"(c[1]), "+f"(c[2]), "+f"(c[3])
        : "r"(a[0]), "r"(a[1]), "r"(a[2]), "r"(a[3]), "r"(b0), "r"(b1));
}
__device__ __forceinline__ float ex2(float x) {
    float y;
    asm("ex2.approx.f32 %0, %1;" : "=f"(y) : "f"(x));
    return y;
}
// Packed fp16x2 exp2: input packed half2, output packed half2.
__device__ __forceinline__ uint32_t h2ex2(uint32_t x) {
    uint32_t y;
    asm("ex2.approx.f16x2 %0, %1;" : "=r"(y) : "r"(x));
    return y;
}
__device__ __forceinline__ uint32_t pack_sub(float a, float b, float m) {
    __half2 h = __floats2half2_rn(a - m, b - m);
    return *(uint32_t*)&h;
}

// ---------------------------------------------------------------------------
// Fused conversion: x, w_qkv, w_out -> fp16 in one launch
// ---------------------------------------------------------------------------
#define NX4 (M_TOTAL * DIN / 4)
#define NQ4 (QKVN * DIN / 4)
#define NO4 (DOUT * DINNER / 4)

__global__ __launch_bounds__(256) void conv_all(
    const float* __restrict__ x, const float* __restrict__ wq,
    const float* __restrict__ wo)
{
    int i = blockIdx.x * 256 + threadIdx.x;
    const float* src;
    __half* dst;
    int j;
    if (i < NX4)                 { src = x;  dst = g_x16; j = i; }
    else if (i < NX4 + NQ4)      { src = wq; dst = g_wqh; j = i - NX4; }
    else if (i < NX4 + NQ4 + NO4){ src = wo; dst = g_woh; j = i - NX4 - NQ4; }
    else return;
    float4 f = ((const float4*)src)[j];
    __half2 a = __floats2half2_rn(f.x, f.y);
    __half2 b = __floats2half2_rn(f.z, f.w);
    uint2 v; v.x = *(uint32_t*)&a; v.y = *(uint32_t*)&b;
    *(uint2*)(dst + j * 4) = v;
}

#define PITCH 40

// ---------------------------------------------------------------------------
// QKV GEMM: tile 128x128x32, 256 threads, warp tile 64x32, single fp16 pass,
// 3-stage cp.async, 2 CTAs/SM. Epilogue -> fp16 q(scaled)/k/v.
// ---------------------------------------------------------------------------
#define ARR_H 10240
#define QSTG2 (2 * ARR_H)
#define QKV_SMEM (3 * QSTG2)

__global__ __launch_bounds__(256, 2) void gemm_qkv128(
    const __half* __restrict__ A, const __half* __restrict__ Bh)
{
    extern __shared__ char smc[];
    const uint32_t sb = smem_u32(smc);
    const int tid = threadIdx.x, lid = tid & 31, wid = tid >> 5;
    const int m0 = blockIdx.y * 128, n0 = blockIdx.x * 128;
    const int mbase = (wid & 1) * 64, nbase = (wid >> 1) * 32;
    const int l8 = lid & 7, lbit = (lid >> 3) & 1, lk = lid >> 4;
    const int K = DIN, nk = DIN >> 5;

    const int row = tid >> 1, cc = (tid & 1) * 16;

    auto issue = [&](int k0, uint32_t stage) {
        const uint32_t d0 = (uint32_t)(row * PITCH + cc) * 2;
        const uint32_t d1 = d0 + 16;
        const __half* a  = A  + (size_t)(m0 + row) * K + k0 + cc;
        const __half* bh = Bh + (size_t)(n0 + row) * K + k0 + cc;
        cpa16(stage + d0, a);           cpa16(stage + d1, a + 8);
        cpa16(stage + ARR_H + d0, bh);  cpa16(stage + ARR_H + d1, bh + 8);
        cp_commit();
    };

    float acc[4][4][4] = {};

    issue(0,  sb);
    issue(32, sb + QSTG2);

    int st = 0, st2 = 2;
    for (int it = 0; it < nk; it++) {
        cp_wait1();
        __syncthreads();
        if (it + 2 < nk) issue((it + 2) << 5, sb + st2 * QSTG2);
        else cp_commit();

        const uint32_t base = sb + st * QSTG2;
        const uint32_t aA = base, aBh = base + ARR_H;

        #pragma unroll
        for (int ks = 0; ks < 32; ks += 16) {
            uint32_t af[4][4], bh[4][2];
            #pragma unroll
            for (int tm = 0; tm < 4; tm++)
                ldsm4(af[tm], aA + (uint32_t)((mbase + tm * 16 + l8 + lbit * 8)
                                              * PITCH + ks + lk * 8) * 2);
            #pragma unroll
            for (int tn = 0; tn < 4; tn++)
                ldsm2(bh[tn], aBh + (uint32_t)((nbase + tn * 8 + l8) * PITCH
                                               + ks + lbit * 8) * 2);
            #pragma unroll
            for (int tm = 0; tm < 4; tm++)
                #pragma unroll
                for (int tn = 0; tn < 4; tn++)
                    mma_f16(acc[tm][tn], af[tm], bh[tn]);
        }
        st  = (st == 2)  ? 0 : st + 1;
        st2 = (st2 == 2) ? 0 : st2 + 1;
    }

    __half* dst = (blockIdx.x == 0) ? g_q : (blockIdx.x == 1 ? g_k : g_v);
    const float scl = (blockIdx.x == 0) ? QSCL : 1.0f;
    #pragma unroll
    for (int tn = 0; tn < 4; tn++) {
        int gc = nbase + tn * 8 + (lid & 3) * 2;
        #pragma unroll
        for (int tm = 0; tm < 4; tm++) {
            int gr = m0 + mbase + tm * 16 + (lid >> 2);
            __half2 h0 = __floats2half2_rn(acc[tm][tn][0] * scl,
                                           acc[tm][tn][1] * scl);
            __half2 h1 = __floats2half2_rn(acc[tm][tn][2] * scl,
                                           acc[tm][tn][3] * scl);
            *(__half2*)(dst + (size_t)gr * DINNER + gc) = h0;
            *(__half2*)(dst + (size_t)(gr + 8) * DINNER + gc) = h1;
        }
    }
}

// ---------------------------------------------------------------------------
// Out GEMM: tile 128x128x32, 256 threads, single fp16 pass, 3-stage.
// Epilogue staged through smem (two 64-row halves) -> coalesced float4 rows.
// ---------------------------------------------------------------------------
#define OARR  10240
#define OSTG  (2 * OARR)
#define GEMM_SMEM (3 * OSTG)

__global__ __launch_bounds__(256, 2) void gemm_out(
    const __half* __restrict__ A, const __half* __restrict__ Bh,
    const float* __restrict__ bias, float* __restrict__ C)
{
    extern __shared__ char smc[];
    const uint32_t sb = smem_u32(smc);
    const int tid = threadIdx.x, lid = tid & 31, wid = tid >> 5;
    const int m0 = blockIdx.y * 128, n0 = blockIdx.x * 128;
    const int mbase = (wid & 1) * 64, nbase = (wid >> 1) * 32;
    const int l8 = lid & 7, lbit = (lid >> 3) & 1, lk = lid >> 4;
    const int K = DINNER, nk = DINNER >> 5;

    const int row = tid >> 1, cc = (tid & 1) * 16;

    auto issue = [&](int k0, uint32_t stage) {
        const uint32_t d0 = (uint32_t)(row * PITCH + cc) * 2;
        const uint32_t d1 = d0 + 16;
        const __half* a  = A  + (size_t)(m0 + row) * K + k0 + cc;
        const __half* bh = Bh + (size_t)(n0 + row) * K + k0 + cc;
        cpa16(stage + d0, a);           cpa16(stage + d1, a + 8);
        cpa16(stage + OARR + d0, bh);   cpa16(stage + OARR + d1, bh + 8);
        cp_commit();
    };

    float acc[4][4][4] = {};

    issue(0,  sb);
    issue(32, sb + OSTG);

    int st = 0, st2 = 2;
    for (int it = 0; it < nk; it++) {
        cp_wait1();
        __syncthreads();
        if (it + 2 < nk) issue((it + 2) << 5, sb + st2 * OSTG);
        else cp_commit();

        const uint32_t base = sb + st * OSTG;
        const uint32_t aA = base, aBh = base + OARR;

        #pragma unroll
        for (int ks = 0; ks < 32; ks += 16) {
            uint32_t af[4][4], bh[2][4];
            #pragma unroll
            for (int tm = 0; tm < 4; tm++)
                ldsm4(af[tm], aA + (uint32_t)((mbase + tm * 16 + l8 + lbit * 8)
                                              * PITCH + ks + lk * 8) * 2);
            #pragma unroll
            for (int bt = 0; bt < 2; bt++)
                ldsm4(bh[bt], aBh + (uint32_t)((nbase + bt * 16 + l8 + lbit * 8)
                                               * PITCH + ks + lk * 8) * 2);
            #pragma unroll
            for (int tm = 0; tm < 4; tm++)
                #pragma unroll
                for (int bt = 0; bt < 2; bt++) {
                    mma_f16b(acc[tm][2 * bt],     af[tm], bh[bt][0], bh[bt][2]);
                    mma_f16b(acc[tm][2 * bt + 1], af[tm], bh[bt][1], bh[bt][3]);
                }
        }
        st  = (st == 2)  ? 0 : st + 1;
        st2 = (st2 == 2) ? 0 : st2 + 1;
    }

    // Epilogue: stage through smem (64 rows x 132 pitch), coalesced stores.
    float* sC = (float*)smc;
    const int halfsel = wid & 1;       // == mbase >> 6
    const float4 b4 = *(const float4*)(bias + n0 + (tid & 31) * 4);
    #pragma unroll
    for (int half = 0; half < 2; half++) {
        __syncthreads();
        if (halfsel == half) {
            #pragma unroll
            for (int tn = 0; tn < 4; tn++) {
                int col = nbase + tn * 8 + (lid & 3) * 2;
                #pragma unroll
                for (int tm = 0; tm < 4; tm++) {
                    int lr = tm * 16 + (lid >> 2);
                    float2 v0; v0.x = acc[tm][tn][0]; v0.y = acc[tm][tn][1];
                    float2 v1; v1.x = acc[tm][tn][2]; v1.y = acc[tm][tn][3];
                    *(float2*)&sC[lr * 132 + col] = v0;
                    *(float2*)&sC[(lr + 8) * 132 + col] = v1;
                }
            }
        }
        __syncthreads();
        #pragma unroll
        for (int i = 0; i < 8; i++) {
            int idx = i * 256 + tid;
            int r = idx >> 5, c4 = idx & 31;
            float4 v = *(float4*)&sC[r * 132 + c4 * 4];
            v.x += b4.x; v.y += b4.y; v.z += b4.z; v.w += b4.w;
            *(float4*)(C + (size_t)(m0 + half * 64 + r) * DOUT + n0 + c4 * 4) = v;
        }
    }
}

// ---------------------------------------------------------------------------
// Split-K flash attention (causal), mma.sync fp16, base-2 softmax via
// ex2.approx.f16x2 (exp results ARE the packed fp16 P fragments). (R13)
// ---------------------------------------------------------------------------
#define AP 136
#define Q_BYTES  (64 * AP * 2)
#define KV_STAGE (2 * Q_BYTES)
#define ATTN_SMEM (Q_BYTES + 2 * KV_STAGE)

__global__ __launch_bounds__(128, 2) void attn_part(
    const __half* __restrict__ gq, const __half* __restrict__ gk,
    const __half* __restrict__ gv, __half* __restrict__ ao,
    float* __restrict__ po, float* __restrict__ pm, float* __restrict__ pl)
{
    extern __shared__ char smc[];
    const int qb = (int)gridDim.x - 1 - (int)blockIdx.x;  // heaviest first
    const int sp = blockIdx.y, b = blockIdx.z;
    const int ntiles = qb + 1;
    const int nsplit = (ntiles + 15) >> 4;
    if (sp >= nsplit) return;
    const int kb0   = (sp * ntiles) / nsplit;
    const int kbend = ((sp + 1) * ntiles) / nsplit;

    const int tid = threadIdx.x, lid = tid & 31, w = tid >> 5;
    const int q0 = qb * 64;
    const int l8 = lid & 7, lbit = (lid >> 3) & 1, lk = lid >> 4;
    const int lq = lid >> 2, lc = lid & 3;
    const size_t rowbase = (size_t)b * SEQ;
    const uint32_t sb = smem_u32(smc);
    __half* sQ = (__half*)smc;

    const int r0c = tid >> 4, cc = tid & 15;

    auto issueKV = [&](int kb, int st) {
        const __half* srcK = gk + (rowbase + (size_t)kb * 64) * DINNER;
        const __half* srcV = gv + (rowbase + (size_t)kb * 64) * DINNER;
        uint32_t dK = sb + Q_BYTES + st * KV_STAGE;
        uint32_t dV = dK + Q_BYTES;
        #pragma unroll
        for (int j = 0; j < 8; j++) {
            int row = r0c + j * 8;
            uint32_t doff = (uint32_t)(row * AP + cc * 8) * 2;
            cpa16(dK + doff, srcK + row * DINNER + cc * 8);
            cpa16(dV + doff, srcV + row * DINNER + cc * 8);
        }
        cp_commit();
    };

    issueKV(kb0, 0);

    #pragma unroll
    for (int i = 0; i < 8; i++) {
        int idx = i * 128 + tid;
        int r = idx >> 4, c = idx & 15;
        *(uint4*)(sQ + r * AP + c * 8) =
            *(const uint4*)(gq + (rowbase + q0 + r) * DINNER + c * 8);
    }
    __syncthreads();

    uint32_t qf[8][4];
    {
        const int arow = w * 16 + l8 + lbit * 8;
        #pragma unroll
        for (int ks = 0; ks < 8; ks++)
            ldsm4(qf[ks], sb + (uint32_t)(arow * AP + ks * 16 + lk * 8) * 2);
    }

    float o[16][4] = {};
    float m0v = -1e30f, m1v = -1e30f, l0v = 0.f, l1v = 0.f;

    for (int kb = kb0; kb < kbend; kb++) {
        const int i = kb - kb0;
        if (kb + 1 < kbend) {
            issueKV(kb + 1, (i + 1) & 1);
            cp_wait1();
        } else {
            cp_wait0();
        }
        __syncthreads();

        const uint32_t bK = sb + Q_BYTES + (i & 1) * KV_STAGE;
        const uint32_t bV = bK + Q_BYTES;

        float s[8][4] = {};
        #pragma unroll
        for (int ks = 0; ks < 8; ks++) {
            #pragma unroll
            for (int tp = 0; tp < 4; tp++) {
                uint32_t bf[4];
                ldsm4(bf, bK + (uint32_t)((tp * 16 + l8 + lk * 8) * AP
                                          + ks * 16 + lbit * 8) * 2);
                mma_f16(s[2 * tp],     qf[ks], bf);
                mma_f16(s[2 * tp + 1], qf[ks], bf + 2);
            }
        }

        if (kb == qb) {
            const int r0 = w * 16 + lq, r1 = r0 + 8;
            #pragma unroll
            for (int t = 0; t < 8; t++) {
                int c0 = t * 8 + lc * 2;
                if (c0 > r0)     s[t][0] = -1e30f;
                if (c0 + 1 > r0) s[t][1] = -1e30f;
                if (c0 > r1)     s[t][2] = -1e30f;
                if (c0 + 1 > r1) s[t][3] = -1e30f;
            }
        }

        float mx0 = -1e30f, mx1 = -1e30f;
        #pragma unroll
        for (int t = 0; t < 8; t++) {
            mx0 = fmaxf(mx0, fmaxf(s[t][0], s[t][1]));
            mx1 = fmaxf(mx1, fmaxf(s[t][2], s[t][3]));
        }
        mx0 = fmaxf(mx0, __shfl_xor_sync(~0u, mx0, 1));
        mx0 = fmaxf(mx0, __shfl_xor_sync(~0u, mx0, 2));
        mx1 = fmaxf(mx1, __shfl_xor_sync(~0u, mx1, 1));
        mx1 = fmaxf(mx1, __shfl_xor_sync(~0u, mx1, 2));
        float mn0 = fmaxf(m0v, mx0), mn1 = fmaxf(m1v, mx1);
        float sc0 = ex2(m0v - mn0), sc1 = ex2(m1v - mn1);

        uint32_t pa[4][4];
        float sum0 = 0.f, sum1 = 0.f;
        #pragma unroll
        for (int t = 0; t < 8; t++) {
            uint32_t e01 = h2ex2(pack_sub(s[t][0], s[t][1], mn0));
            uint32_t e23 = h2ex2(pack_sub(s[t][2], s[t][3], mn1));
            pa[t >> 1][(t & 1) * 2]     = e01;
            pa[t >> 1][(t & 1) * 2 + 1] = e23;
            float2 f01 = __half22float2(*(__half2*)&e01);
            float2 f23 = __half22float2(*(__half2*)&e23);
            sum0 += f01.x + f01.y;
            sum1 += f23.x + f23.y;
        }
        sum0 += __shfl_xor_sync(~0u, sum0, 1);
        sum0 += __shfl_xor_sync(~0u, sum0, 2);
        sum1 += __shfl_xor_sync(~0u, sum1, 1);
        sum1 += __shfl_xor_sync(~0u, sum1, 2);
        l0v = l0v * sc0 + sum0;  l1v = l1v * sc1 + sum1;
        m0v = mn0;  m1v = mn1;
        #pragma unroll
        for (int t = 0; t < 16; t++) {
            o[t][0] *= sc0; o[t][1] *= sc0;
            o[t][2] *= sc1; o[t][3] *= sc1;
        }

        #pragma unroll
        for (int c = 0; c < 4; c++) {
            #pragma unroll
            for (int dp = 0; dp < 8; dp++) {
                uint32_t vf[4];
                ldsm4t(vf, bV + (uint32_t)((c * 16 + l8 + lbit * 8) * AP
                                           + dp * 16 + lk * 8) * 2);
                mma_f16(o[2 * dp],     pa[c], vf);
                mma_f16(o[2 * dp + 1], pa[c], vf + 2);
            }
        }
        __syncthreads();
    }

    const int lr0 = w * 16 + lq, lr1 = lr0 + 8;

    if (nsplit == 1) {
        const float inv0 = 1.f / l0v, inv1 = 1.f / l1v;
        const size_t gr0 = rowbase + q0 + lr0;
        #pragma unroll
        for (int t = 0; t < 16; t++) {
            int col = t * 8 + lc * 2;
            *(__half2*)(ao + gr0 * DINNER + col) =
                __floats2half2_rn(o[t][0] * inv0, o[t][1] * inv0);
            *(__half2*)(ao + (gr0 + 8) * DINNER + col) =
                __floats2half2_rn(o[t][2] * inv1, o[t][3] * inv1);
        }
    } else {
        const size_t pidx = ((size_t)(b * 64 + qb)) * 4 + sp;
        float* pob = po + pidx * (64 * DINNER);
        #pragma unroll
        for (int t = 0; t < 16; t++) {
            int col = t * 8 + lc * 2;
            float2 v0; v0.x = o[t][0]; v0.y = o[t][1];
            float2 v1; v1.x = o[t][2]; v1.y = o[t][3];
            *(float2*)(pob + lr0 * DINNER + col) = v0;
            *(float2*)(pob + lr1 * DINNER + col) = v1;
        }
        if (lc == 0) {
            pm[pidx * 64 + lr0] = m0v;  pm[pidx * 64 + lr1] = m1v;
            pl[pidx * 64 + lr0] = l0v;  pl[pidx * 64 + lr1] = l1v;
        }
    }
}

// ---------------------------------------------------------------------------
// Combine partials -> fp16 attention output. Grid (96, BATCH):
// qb = 16 + bx/2; each block handles 64 columns; 8 cols/thread.
// ---------------------------------------------------------------------------
__global__ __launch_bounds__(512) void attn_combine(
    const float* __restrict__ po, const float* __restrict__ pm,
    const float* __restrict__ pl, __half* __restrict__ ao)
{
    const int qb = (blockIdx.x >> 1) + 16;
    const int coff = (blockIdx.x & 1) * 64;
    const int b = blockIdx.y;
    const int nsplit = (qb >> 4) + 1;
    const int t = threadIdx.x;
    const int r = t >> 3, c0 = coff + (t & 7) * 8;
    const size_t base = ((size_t)(b * 64 + qb)) * 4;

    float mg = -1e30f;
    #pragma unroll
    for (int s = 0; s < 4; s++)
        if (s < nsplit) mg = fmaxf(mg, pm[(base + s) * 64 + r]);
    float wgt[4] = {};
    float L = 0.f;
    #pragma unroll
    for (int s = 0; s < 4; s++)
        if (s < nsplit) {
            wgt[s] = ex2(pm[(base + s) * 64 + r] - mg);
            L += wgt[s] * pl[(base + s) * 64 + r];
        }
    const float inv = 1.f / L;

    float4 acc[2] = {};
    #pragma unroll
    for (int s = 0; s < 4; s++)
        if (s < nsplit) {
            const float4* p = (const float4*)(po + (base + s) * (64 * DINNER)
                                              + r * DINNER + c0);
            const float wv = wgt[s];
            #pragma unroll
            for (int j = 0; j < 2; j++) {
                float4 v = p[j];
                acc[j].x += wv * v.x; acc[j].y += wv * v.y;
                acc[j].z += wv * v.z; acc[j].w += wv * v.w;
            }
        }

    __half2 hb[4];
    #pragma unroll
    for (int j = 0; j < 2; j++) {
        hb[2 * j]     = __floats2half2_rn(acc[j].x * inv, acc[j].y * inv);
        hb[2 * j + 1] = __floats2half2_rn(acc[j].z * inv, acc[j].w * inv);
    }
    const size_t grow = (size_t)b * SEQ + qb * 64 + r;
    *(uint4*)(ao + grow * DINNER + c0) = *(uint4*)&hb[0];
}

// ---------------------------------------------------------------------------
extern "C" void kernel_launch(void* const* d_in, const int* in_sizes, int n_in,
                              void* d_out, int out_size)
{
    const float* x     = (const float*)d_in[0];
    const float* w_qkv = (const float*)d_in[1];
    const float* w_out = (const float*)d_in[2];
    const float* b_out = (const float*)d_in[3];
    float* out = (float*)d_out;

    __half *x16, *wqh, *woh, *q_p, *k_p, *v_p, *ao;
    float *po, *pmv, *plv;
    cudaGetSymbolAddress((void**)&x16, g_x16);
    cudaGetSymbolAddress((void**)&wqh, g_wqh);
    cudaGetSymbolAddress((void**)&woh, g_woh);
    cudaGetSymbolAddress((void**)&q_p, g_q);
    cudaGetSymbolAddress((void**)&k_p, g_k);
    cudaGetSymbolAddress((void**)&v_p, g_v);
    cudaGetSymbolAddress((void**)&ao, g_ao);
    cudaGetSymbolAddress((void**)&po, g_po);
    cudaGetSymbolAddress((void**)&pmv, g_pm);
    cudaGetSymbolAddress((void**)&plv, g_pl);

    cudaFuncSetAttribute(gemm_qkv128, cudaFuncAttributeMaxDynamicSharedMemorySize,
                         QKV_SMEM);
    cudaFuncSetAttribute(gemm_out, cudaFuncAttributeMaxDynamicSharedMemorySize,
                         GEMM_SMEM);
    cudaFuncSetAttribute(attn_part, cudaFuncAttributeMaxDynamicSharedMemorySize,
                         ATTN_SMEM);

    // 0) Fused conversions: x, w_qkv, w_out -> fp16
    conv_all<<<(NX4 + NQ4 + NO4 + 255) / 256, 256>>>(x, w_qkv, w_out);

    // 1) QKV projection (128x128 tile, 64x32 warp, single fp16 pass)
    gemm_qkv128<<<dim3(QKVN / 128, M_TOTAL / 128), 256, QKV_SMEM>>>(x16, wqh);

    // 2) Split-K causal flash attention -> fp16 (balanced splits)
    attn_part<<<dim3(SEQ / 64, 4, BATCH), 128, ATTN_SMEM>>>(
        q_p, k_p, v_p, ao, po, pmv, plv);
    attn_combine<<<dim3(96, BATCH), 512>>>(po, pmv, plv, ao);

    // 3) Output projection + bias (smem-staged coalesced epilogue)
    gemm_out<<<dim3(DOUT / 128, M_TOTAL / 128), 256, GEMM_SMEM>>>(
        ao, woh, b_out, out);
}

// round 17
// speedup vs baseline: 1.0296x; 1.0296x over previous
#include <cuda_runtime.h>
#include <cuda_fp16.h>
#include <cstdint>

#define BATCH   4
#define SEQ     4096
#define DIN     1024
#define DINNER  128
#define DOUT    1024
#define QKVN    384
#define M_TOTAL (BATCH * SEQ)
// SCALE * log2(e): softmax runs in base-2 domain
#define QSCL    0.12751744f

// Scratch
__device__ __half g_x16[(size_t)M_TOTAL * DIN];
__device__ __half g_wqh[QKVN * DIN];
__device__ __half g_woh[DOUT * DINNER];
__device__ __half g_q[(size_t)M_TOTAL * DINNER];
__device__ __half g_k[(size_t)M_TOTAL * DINNER];
__device__ __half g_v[(size_t)M_TOTAL * DINNER];
__device__ __half g_ao[(size_t)M_TOTAL * DINNER];
__device__ float g_po[(size_t)BATCH * 64 * 4 * 64 * DINNER];
__device__ float g_pm[BATCH * 64 * 4 * 64];
__device__ float g_pl[BATCH * 64 * 4 * 64];

// ---------------------------------------------------------------------------
// PTX helpers
// ---------------------------------------------------------------------------
__device__ __forceinline__ uint32_t smem_u32(const void* p) {
    uint32_t a;
    asm("{ .reg .u64 t; cvta.to.shared.u64 t, %1; cvt.u32.u64 %0, t; }"
        : "=r"(a) : "l"(p));
    return a;
}
__device__ __forceinline__ void cpa16(uint32_t dst, const void* src) {
    asm volatile("cp.async.cg.shared.global [%0], [%1], 16;"
                 :: "r"(dst), "l"(src));
}
__device__ __forceinline__ void cp_commit() {
    asm volatile("cp.async.commit_group;" ::: "memory");
}
__device__ __forceinline__ void cp_wait1() {
    asm volatile("cp.async.wait_group 1;" ::: "memory");
}
__device__ __forceinline__ void cp_wait0() {
    asm volatile("cp.async.wait_group 0;" ::: "memory");
}
__device__ __forceinline__ void ldsm4(uint32_t* r, uint32_t a) {
    asm volatile("ldmatrix.sync.aligned.m8n8.x4.shared.b16 {%0,%1,%2,%3}, [%4];"
        : "=r"(r[0]), "=r"(r[1]), "=r"(r[2]), "=r"(r[3]) : "r"(a));
}
__device__ __forceinline__ void ldsm4t(uint32_t* r, uint32_t a) {
    asm volatile("ldmatrix.sync.aligned.m8n8.x4.trans.shared.b16 {%0,%1,%2,%3}, [%4];"
        : "=r"(r[0]), "=r"(r[1]), "=r"(r[2]), "=r"(r[3]) : "r"(a));
}
__device__ __forceinline__ void ldsm2(uint32_t* r, uint32_t a) {
    asm volatile("ldmatrix.sync.aligned.m8n8.x2.shared.b16 {%0,%1}, [%2];"
        : "=r"(r[0]), "=r"(r[1]) : "r"(a));
}
__device__ __forceinline__ void mma_f16(float* c, const uint32_t* a,
                                        const uint32_t* b) {
    asm volatile(
        "mma.sync.aligned.m16n8k16.row.col.f32.f16.f16.f32 "
        "{%0,%1,%2,%3}, {%4,%5,%6,%7}, {%8,%9}, {%0,%1,%2,%3};"
        : "+f"(c[0]), "+f"(c[1]), "+f"(c[2]), "+f"(c[3])
        : "r"(a[0]), "r"(a[1]), "r"(a[2]), "r"(a[3]), "r"(b[0]), "r"(b[1]));
}
__device__ __forceinline__ void mma_f16b(float* c, const uint32_t* a,
                                         uint32_t b0, uint32_t b1) {
    asm volatile(
        "mma.sync.aligned.m16n8k16.row.col.f32.f16.f16.f32 "
        "{%0,%1,%2,%3}, {%4,%5,%6,%7}, {%8,%9}, {%0,%1,%2,%3};"
        : "+f"(c[0]), "+f"(c[1]), "+f"(c[2]), "+f"(c[3])
        : "r"(a[0]), "r"(a[1]), "r"(a[2]), "r"(a[3]), "r"(b0), "r"(b1));
}
__device__ __forceinline__ float ex2(float x) {
    float y;
    asm("ex2.approx.f32 %0, %1;" : "=f"(y) : "f"(x));
    return y;
}
// Packed fp16x2 exp2: input packed half2, output packed half2.
__device__ __forceinline__ uint32_t h2ex2(uint32_t x) {
    uint32_t y;
    asm("ex2.approx.f16x2 %0, %1;" : "=r"(y) : "r"(x));
    return y;
}
__device__ __forceinline__ uint32_t pack_sub(float a, float b, float m) {
    __half2 h = __floats2half2_rn(a - m, b - m);
    return *(uint32_t*)&h;
}

// ---------------------------------------------------------------------------
// Fused conversion: x, w_qkv, w_out -> fp16 in one launch
// ---------------------------------------------------------------------------
#define NX4 (M_TOTAL * DIN / 4)
#define NQ4 (QKVN * DIN / 4)
#define NO4 (DOUT * DINNER / 4)

__global__ __launch_bounds__(256) void conv_all(
    const float* __restrict__ x, const float* __restrict__ wq,
    const float* __restrict__ wo)
{
    int i = blockIdx.x * 256 + threadIdx.x;
    const float* src;
    __half* dst;
    int j;
    if (i < NX4)                 { src = x;  dst = g_x16; j = i; }
    else if (i < NX4 + NQ4)      { src = wq; dst = g_wqh; j = i - NX4; }
    else if (i < NX4 + NQ4 + NO4){ src = wo; dst = g_woh; j = i - NX4 - NQ4; }
    else return;
    float4 f = ((const float4*)src)[j];
    __half2 a = __floats2half2_rn(f.x, f.y);
    __half2 b = __floats2half2_rn(f.z, f.w);
    uint2 v; v.x = *(uint32_t*)&a; v.y = *(uint32_t*)&b;
    *(uint2*)(dst + j * 4) = v;
}

#define PITCH 40

// ---------------------------------------------------------------------------
// QKV GEMM: tile 128x128x32, 256 threads, warp tile 64x32, single fp16 pass,
// 3-stage cp.async, 2 CTAs/SM. Epilogue -> fp16 q(scaled)/k/v.
// ---------------------------------------------------------------------------
#define ARR_H 10240
#define QSTG2 (2 * ARR_H)
#define QKV_SMEM (3 * QSTG2)

__global__ __launch_bounds__(256, 2) void gemm_qkv128(
    const __half* __restrict__ A, const __half* __restrict__ Bh)
{
    extern __shared__ char smc[];
    const uint32_t sb = smem_u32(smc);
    const int tid = threadIdx.x, lid = tid & 31, wid = tid >> 5;
    const int m0 = blockIdx.y * 128, n0 = blockIdx.x * 128;
    const int mbase = (wid & 1) * 64, nbase = (wid >> 1) * 32;
    const int l8 = lid & 7, lbit = (lid >> 3) & 1, lk = lid >> 4;
    const int K = DIN, nk = DIN >> 5;

    const int row = tid >> 1, cc = (tid & 1) * 16;

    auto issue = [&](int k0, uint32_t stage) {
        const uint32_t d0 = (uint32_t)(row * PITCH + cc) * 2;
        const uint32_t d1 = d0 + 16;
        const __half* a  = A  + (size_t)(m0 + row) * K + k0 + cc;
        const __half* bh = Bh + (size_t)(n0 + row) * K + k0 + cc;
        cpa16(stage + d0, a);           cpa16(stage + d1, a + 8);
        cpa16(stage + ARR_H + d0, bh);  cpa16(stage + ARR_H + d1, bh + 8);
        cp_commit();
    };

    float acc[4][4][4] = {};

    issue(0,  sb);
    issue(32, sb + QSTG2);

    int st = 0, st2 = 2;
    for (int it = 0; it < nk; it++) {
        cp_wait1();
        __syncthreads();
        if (it + 2 < nk) issue((it + 2) << 5, sb + st2 * QSTG2);
        else cp_commit();

        const uint32_t base = sb + st * QSTG2;
        const uint32_t aA = base, aBh = base + ARR_H;

        #pragma unroll
        for (int ks = 0; ks < 32; ks += 16) {
            uint32_t af[4][4], bh[4][2];
            #pragma unroll
            for (int tm = 0; tm < 4; tm++)
                ldsm4(af[tm], aA + (uint32_t)((mbase + tm * 16 + l8 + lbit * 8)
                                              * PITCH + ks + lk * 8) * 2);
            #pragma unroll
            for (int tn = 0; tn < 4; tn++)
                ldsm2(bh[tn], aBh + (uint32_t)((nbase + tn * 8 + l8) * PITCH
                                               + ks + lbit * 8) * 2);
            #pragma unroll
            for (int tm = 0; tm < 4; tm++)
                #pragma unroll
                for (int tn = 0; tn < 4; tn++)
                    mma_f16(acc[tm][tn], af[tm], bh[tn]);
        }
        st  = (st == 2)  ? 0 : st + 1;
        st2 = (st2 == 2) ? 0 : st2 + 1;
    }

    __half* dst = (blockIdx.x == 0) ? g_q : (blockIdx.x == 1 ? g_k : g_v);
    const float scl = (blockIdx.x == 0) ? QSCL : 1.0f;
    #pragma unroll
    for (int tn = 0; tn < 4; tn++) {
        int gc = nbase + tn * 8 + (lid & 3) * 2;
        #pragma unroll
        for (int tm = 0; tm < 4; tm++) {
            int gr = m0 + mbase + tm * 16 + (lid >> 2);
            __half2 h0 = __floats2half2_rn(acc[tm][tn][0] * scl,
                                           acc[tm][tn][1] * scl);
            __half2 h1 = __floats2half2_rn(acc[tm][tn][2] * scl,
                                           acc[tm][tn][3] * scl);
            *(__half2*)(dst + (size_t)gr * DINNER + gc) = h0;
            *(__half2*)(dst + (size_t)(gr + 8) * DINNER + gc) = h1;
        }
    }
}

// ---------------------------------------------------------------------------
// Out GEMM: tile 128x128x32, 256 threads, single fp16 pass, 3-stage.
// Direct float2 epilogue (R15 version — smem staging regressed).
// ---------------------------------------------------------------------------
#define OARR  10240
#define OSTG  (2 * OARR)
#define GEMM_SMEM (3 * OSTG)

__global__ __launch_bounds__(256, 2) void gemm_out(
    const __half* __restrict__ A, const __half* __restrict__ Bh,
    const float* __restrict__ bias, float* __restrict__ C)
{
    extern __shared__ char smc[];
    const uint32_t sb = smem_u32(smc);
    const int tid = threadIdx.x, lid = tid & 31, wid = tid >> 5;
    const int m0 = blockIdx.y * 128, n0 = blockIdx.x * 128;
    const int mbase = (wid & 1) * 64, nbase = (wid >> 1) * 32;
    const int l8 = lid & 7, lbit = (lid >> 3) & 1, lk = lid >> 4;
    const int K = DINNER, nk = DINNER >> 5;

    const int row = tid >> 1, cc = (tid & 1) * 16;

    auto issue = [&](int k0, uint32_t stage) {
        const uint32_t d0 = (uint32_t)(row * PITCH + cc) * 2;
        const uint32_t d1 = d0 + 16;
        const __half* a  = A  + (size_t)(m0 + row) * K + k0 + cc;
        const __half* bh = Bh + (size_t)(n0 + row) * K + k0 + cc;
        cpa16(stage + d0, a);           cpa16(stage + d1, a + 8);
        cpa16(stage + OARR + d0, bh);   cpa16(stage + OARR + d1, bh + 8);
        cp_commit();
    };

    float acc[4][4][4] = {};

    issue(0,  sb);
    issue(32, sb + OSTG);

    int st = 0, st2 = 2;
    for (int it = 0; it < nk; it++) {
        cp_wait1();
        __syncthreads();
        if (it + 2 < nk) issue((it + 2) << 5, sb + st2 * OSTG);
        else cp_commit();

        const uint32_t base = sb + st * OSTG;
        const uint32_t aA = base, aBh = base + OARR;

        #pragma unroll
        for (int ks = 0; ks < 32; ks += 16) {
            uint32_t af[4][4], bh[2][4];
            #pragma unroll
            for (int tm = 0; tm < 4; tm++)
                ldsm4(af[tm], aA + (uint32_t)((mbase + tm * 16 + l8 + lbit * 8)
                                              * PITCH + ks + lk * 8) * 2);
            #pragma unroll
            for (int bt = 0; bt < 2; bt++)
                ldsm4(bh[bt], aBh + (uint32_t)((nbase + bt * 16 + l8 + lbit * 8)
                                               * PITCH + ks + lk * 8) * 2);
            #pragma unroll
            for (int tm = 0; tm < 4; tm++)
                #pragma unroll
                for (int bt = 0; bt < 2; bt++) {
                    mma_f16b(acc[tm][2 * bt],     af[tm], bh[bt][0], bh[bt][2]);
                    mma_f16b(acc[tm][2 * bt + 1], af[tm], bh[bt][1], bh[bt][3]);
                }
        }
        st  = (st == 2)  ? 0 : st + 1;
        st2 = (st2 == 2) ? 0 : st2 + 1;
    }

    #pragma unroll
    for (int tn = 0; tn < 4; tn++) {
        int gc = n0 + nbase + tn * 8 + (lid & 3) * 2;
        float bx = bias[gc], by = bias[gc + 1];
        #pragma unroll
        for (int tm = 0; tm < 4; tm++) {
            int gr = m0 + mbase + tm * 16 + (lid >> 2);
            float2 v0, v1;
            v0.x = acc[tm][tn][0] + bx; v0.y = acc[tm][tn][1] + by;
            v1.x = acc[tm][tn][2] + bx; v1.y = acc[tm][tn][3] + by;
            *(float2*)(C + (size_t)gr * DOUT + gc) = v0;
            *(float2*)(C + (size_t)(gr + 8) * DOUT + gc) = v1;
        }
    }
}

// ---------------------------------------------------------------------------
// Split-K flash attention (causal), mma.sync fp16, base-2 softmax via
// ex2.approx.f16x2 (exp results ARE the packed fp16 P fragments).
// ---------------------------------------------------------------------------
#define AP 136
#define Q_BYTES  (64 * AP * 2)
#define KV_STAGE (2 * Q_BYTES)
#define ATTN_SMEM (Q_BYTES + 2 * KV_STAGE)

__global__ __launch_bounds__(128, 2) void attn_part(
    const __half* __restrict__ gq, const __half* __restrict__ gk,
    const __half* __restrict__ gv, __half* __restrict__ ao,
    float* __restrict__ po, float* __restrict__ pm, float* __restrict__ pl)
{
    extern __shared__ char smc[];
    const int qb = (int)gridDim.x - 1 - (int)blockIdx.x;  // heaviest first
    const int sp = blockIdx.y, b = blockIdx.z;
    const int ntiles = qb + 1;
    const int nsplit = (ntiles + 15) >> 4;
    if (sp >= nsplit) return;
    const int kb0   = (sp * ntiles) / nsplit;
    const int kbend = ((sp + 1) * ntiles) / nsplit;

    const int tid = threadIdx.x, lid = tid & 31, w = tid >> 5;
    const int q0 = qb * 64;
    const int l8 = lid & 7, lbit = (lid >> 3) & 1, lk = lid >> 4;
    const int lq = lid >> 2, lc = lid & 3;
    const size_t rowbase = (size_t)b * SEQ;
    const uint32_t sb = smem_u32(smc);
    __half* sQ = (__half*)smc;

    const int r0c = tid >> 4, cc = tid & 15;

    auto issueKV = [&](int kb, int st) {
        const __half* srcK = gk + (rowbase + (size_t)kb * 64) * DINNER;
        const __half* srcV = gv + (rowbase + (size_t)kb * 64) * DINNER;
        uint32_t dK = sb + Q_BYTES + st * KV_STAGE;
        uint32_t dV = dK + Q_BYTES;
        #pragma unroll
        for (int j = 0; j < 8; j++) {
            int row = r0c + j * 8;
            uint32_t doff = (uint32_t)(row * AP + cc * 8) * 2;
            cpa16(dK + doff, srcK + row * DINNER + cc * 8);
            cpa16(dV + doff, srcV + row * DINNER + cc * 8);
        }
        cp_commit();
    };

    issueKV(kb0, 0);

    #pragma unroll
    for (int i = 0; i < 8; i++) {
        int idx = i * 128 + tid;
        int r = idx >> 4, c = idx & 15;
        *(uint4*)(sQ + r * AP + c * 8) =
            *(const uint4*)(gq + (rowbase + q0 + r) * DINNER + c * 8);
    }
    __syncthreads();

    uint32_t qf[8][4];
    {
        const int arow = w * 16 + l8 + lbit * 8;
        #pragma unroll
        for (int ks = 0; ks < 8; ks++)
            ldsm4(qf[ks], sb + (uint32_t)(arow * AP + ks * 16 + lk * 8) * 2);
    }

    float o[16][4] = {};
    float m0v = -1e30f, m1v = -1e30f, l0v = 0.f, l1v = 0.f;

    for (int kb = kb0; kb < kbend; kb++) {
        const int i = kb - kb0;
        if (kb + 1 < kbend) {
            issueKV(kb + 1, (i + 1) & 1);
            cp_wait1();
        } else {
            cp_wait0();
        }
        __syncthreads();

        const uint32_t bK = sb + Q_BYTES + (i & 1) * KV_STAGE;
        const uint32_t bV = bK + Q_BYTES;

        float s[8][4] = {};
        #pragma unroll
        for (int ks = 0; ks < 8; ks++) {
            #pragma unroll
            for (int tp = 0; tp < 4; tp++) {
                uint32_t bf[4];
                ldsm4(bf, bK + (uint32_t)((tp * 16 + l8 + lk * 8) * AP
                                          + ks * 16 + lbit * 8) * 2);
                mma_f16(s[2 * tp],     qf[ks], bf);
                mma_f16(s[2 * tp + 1], qf[ks], bf + 2);
            }
        }

        if (kb == qb) {
            const int r0 = w * 16 + lq, r1 = r0 + 8;
            #pragma unroll
            for (int t = 0; t < 8; t++) {
                int c0 = t * 8 + lc * 2;
                if (c0 > r0)     s[t][0] = -1e30f;
                if (c0 + 1 > r0) s[t][1] = -1e30f;
                if (c0 > r1)     s[t][2] = -1e30f;
                if (c0 + 1 > r1) s[t][3] = -1e30f;
            }
        }

        float mx0 = -1e30f, mx1 = -1e30f;
        #pragma unroll
        for (int t = 0; t < 8; t++) {
            mx0 = fmaxf(mx0, fmaxf(s[t][0], s[t][1]));
            mx1 = fmaxf(mx1, fmaxf(s[t][2], s[t][3]));
        }
        mx0 = fmaxf(mx0, __shfl_xor_sync(~0u, mx0, 1));
        mx0 = fmaxf(mx0, __shfl_xor_sync(~0u, mx0, 2));
        mx1 = fmaxf(mx1, __shfl_xor_sync(~0u, mx1, 1));
        mx1 = fmaxf(mx1, __shfl_xor_sync(~0u, mx1, 2));
        float mn0 = fmaxf(m0v, mx0), mn1 = fmaxf(m1v, mx1);
        float sc0 = ex2(m0v - mn0), sc1 = ex2(m1v - mn1);

        uint32_t pa[4][4];
        float sum0 = 0.f, sum1 = 0.f;
        #pragma unroll
        for (int t = 0; t < 8; t++) {
            uint32_t e01 = h2ex2(pack_sub(s[t][0], s[t][1], mn0));
            uint32_t e23 = h2ex2(pack_sub(s[t][2], s[t][3], mn1));
            pa[t >> 1][(t & 1) * 2]     = e01;
            pa[t >> 1][(t & 1) * 2 + 1] = e23;
            float2 f01 = __half22float2(*(__half2*)&e01);
            float2 f23 = __half22float2(*(__half2*)&e23);
            sum0 += f01.x + f01.y;
            sum1 += f23.x + f23.y;
        }
        sum0 += __shfl_xor_sync(~0u, sum0, 1);
        sum0 += __shfl_xor_sync(~0u, sum0, 2);
        sum1 += __shfl_xor_sync(~0u, sum1, 1);
        sum1 += __shfl_xor_sync(~0u, sum1, 2);
        l0v = l0v * sc0 + sum0;  l1v = l1v * sc1 + sum1;
        m0v = mn0;  m1v = mn1;
        #pragma unroll
        for (int t = 0; t < 16; t++) {
            o[t][0] *= sc0; o[t][1] *= sc0;
            o[t][2] *= sc1; o[t][3] *= sc1;
        }

        #pragma unroll
        for (int c = 0; c < 4; c++) {
            #pragma unroll
            for (int dp = 0; dp < 8; dp++) {
                uint32_t vf[4];
                ldsm4t(vf, bV + (uint32_t)((c * 16 + l8 + lbit * 8) * AP
                                           + dp * 16 + lk * 8) * 2);
                mma_f16(o[2 * dp],     pa[c], vf);
                mma_f16(o[2 * dp + 1], pa[c], vf + 2);
            }
        }
        __syncthreads();
    }

    const int lr0 = w * 16 + lq, lr1 = lr0 + 8;

    if (nsplit == 1) {
        const float inv0 = 1.f / l0v, inv1 = 1.f / l1v;
        const size_t gr0 = rowbase + q0 + lr0;
        #pragma unroll
        for (int t = 0; t < 16; t++) {
            int col = t * 8 + lc * 2;
            *(__half2*)(ao + gr0 * DINNER + col) =
                __floats2half2_rn(o[t][0] * inv0, o[t][1] * inv0);
            *(__half2*)(ao + (gr0 + 8) * DINNER + col) =
                __floats2half2_rn(o[t][2] * inv1, o[t][3] * inv1);
        }
    } else {
        const size_t pidx = ((size_t)(b * 64 + qb)) * 4 + sp;
        float* pob = po + pidx * (64 * DINNER);
        #pragma unroll
        for (int t = 0; t < 16; t++) {
            int col = t * 8 + lc * 2;
            float2 v0; v0.x = o[t][0]; v0.y = o[t][1];
            float2 v1; v1.x = o[t][2]; v1.y = o[t][3];
            *(float2*)(pob + lr0 * DINNER + col) = v0;
            *(float2*)(pob + lr1 * DINNER + col) = v1;
        }
        if (lc == 0) {
            pm[pidx * 64 + lr0] = m0v;  pm[pidx * 64 + lr1] = m1v;
            pl[pidx * 64 + lr0] = l0v;  pl[pidx * 64 + lr1] = l1v;
        }
    }
}

// ---------------------------------------------------------------------------
// Combine partials -> fp16 attention output. Grid (96, BATCH):
// qb = 16 + bx/2; each block handles 64 columns; 8 cols/thread. (R16 version)
// ---------------------------------------------------------------------------
__global__ __launch_bounds__(512) void attn_combine(
    const float* __restrict__ po, const float* __restrict__ pm,
    const float* __restrict__ pl, __half* __restrict__ ao)
{
    const int qb = (blockIdx.x >> 1) + 16;
    const int coff = (blockIdx.x & 1) * 64;
    const int b = blockIdx.y;
    const int nsplit = (qb >> 4) + 1;
    const int t = threadIdx.x;
    const int r = t >> 3, c0 = coff + (t & 7) * 8;
    const size_t base = ((size_t)(b * 64 + qb)) * 4;

    float mg = -1e30f;
    #pragma unroll
    for (int s = 0; s < 4; s++)
        if (s < nsplit) mg = fmaxf(mg, pm[(base + s) * 64 + r]);
    float wgt[4] = {};
    float L = 0.f;
    #pragma unroll
    for (int s = 0; s < 4; s++)
        if (s < nsplit) {
            wgt[s] = ex2(pm[(base + s) * 64 + r] - mg);
            L += wgt[s] * pl[(base + s) * 64 + r];
        }
    const float inv = 1.f / L;

    float4 acc[2] = {};
    #pragma unroll
    for (int s = 0; s < 4; s++)
        if (s < nsplit) {
            const float4* p = (const float4*)(po + (base + s) * (64 * DINNER)
                                              + r * DINNER + c0);
            const float wv = wgt[s];
            #pragma unroll
            for (int j = 0; j < 2; j++) {
                float4 v = p[j];
                acc[j].x += wv * v.x; acc[j].y += wv * v.y;
                acc[j].z += wv * v.z; acc[j].w += wv * v.w;
            }
        }

    __half2 hb[4];
    #pragma unroll
    for (int j = 0; j < 2; j++) {
        hb[2 * j]     = __floats2half2_rn(acc[j].x * inv, acc[j].y * inv);
        hb[2 * j + 1] = __floats2half2_rn(acc[j].z * inv, acc[j].w * inv);
    }
    const size_t grow = (size_t)b * SEQ + qb * 64 + r;
    *(uint4*)(ao + grow * DINNER + c0) = *(uint4*)&hb[0];
}

// ---------------------------------------------------------------------------
extern "C" void kernel_launch(void* const* d_in, const int* in_sizes, int n_in,
                              void* d_out, int out_size)
{
    const float* x     = (const float*)d_in[0];
    const float* w_qkv = (const float*)d_in[1];
    const float* w_out = (const float*)d_in[2];
    const float* b_out = (const float*)d_in[3];
    float* out = (float*)d_out;

    __half *x16, *wqh, *woh, *q_p, *k_p, *v_p, *ao;
    float *po, *pmv, *plv;
    cudaGetSymbolAddress((void**)&x16, g_x16);
    cudaGetSymbolAddress((void**)&wqh, g_wqh);
    cudaGetSymbolAddress((void**)&woh, g_woh);
    cudaGetSymbolAddress((void**)&q_p, g_q);
    cudaGetSymbolAddress((void**)&k_p, g_k);
    cudaGetSymbolAddress((void**)&v_p, g_v);
    cudaGetSymbolAddress((void**)&ao, g_ao);
    cudaGetSymbolAddress((void**)&po, g_po);
    cudaGetSymbolAddress((void**)&pmv, g_pm);
    cudaGetSymbolAddress((void**)&plv, g_pl);

    cudaFuncSetAttribute(gemm_qkv128, cudaFuncAttributeMaxDynamicSharedMemorySize,
                         QKV_SMEM);
    cudaFuncSetAttribute(gemm_out, cudaFuncAttributeMaxDynamicSharedMemorySize,
                         GEMM_SMEM);
    cudaFuncSetAttribute(attn_part, cudaFuncAttributeMaxDynamicSharedMemorySize,
                         ATTN_SMEM);

    // 0) Fused conversions: x, w_qkv, w_out -> fp16
    conv_all<<<(NX4 + NQ4 + NO4 + 255) / 256, 256>>>(x, w_qkv, w_out);

    // 1) QKV projection (128x128 tile, 64x32 warp, single fp16 pass)
    gemm_qkv128<<<dim3(QKVN / 128, M_TOTAL / 128), 256, QKV_SMEM>>>(x16, wqh);

    // 2) Split-K causal flash attention -> fp16 (balanced splits)
    attn_part<<<dim3(SEQ / 64, 4, BATCH), 128, ATTN_SMEM>>>(
        q_p, k_p, v_p, ao, po, pmv, plv);
    attn_combine<<<dim3(96, BATCH), 512>>>(po, pmv, plv, ao);

    // 3) Output projection + bias (direct float2 epilogue, R15 version)
    gemm_out<<<dim3(DOUT / 128, M_TOTAL / 128), 256, GEMM_SMEM>>>(
        ao, woh, b_out, out);
}